// round 8
// baseline (speedup 1.0000x reference)
#include <cuda_runtime.h>
#include <cuda_bf16.h>

// JointBilateral upsample, S=4, K=5. Block = 128 threads = 4 output rows x
// 128 cols: ql = tid&31 (cols 4q..4q+3, q = qb*32+ql), s = tid>>5 (row).
// s is warp-uniform; each warp's center load = one contiguous 512B segment.
// Taps shared through smem: s==1 publishes first-tap (= its center .y) + x;
// s==3 publishes second-row tap + x. Lane 31 loads the q+1 halo.
//
// e(tap) = exp(-0.125*||g_tap - g_ctr||^2) * exp(-0.005*((i-2)^2+(j-2)^2))
// out = sum(e * wgt[4-i][4-j] * x_tap) / sum(e)
// MUFU-free: cubic exp(-z) for z in [0,0.094], Newton reciprocal.

#define CH  (512 * 512)
#define E1  0.9950124791926823f   /* exp(-0.005) */
#define E4  0.9801986733067553f   /* exp(-0.020) */

__device__ __forceinline__ float exp_neg_small(float z)
{
    float p = fmaf(-0.16666667f, z, 0.5f);
    p = fmaf(p, z, -1.0f);
    return fmaf(p, z, 1.0f);
}

__device__ __forceinline__ float fast_rcp(float x)
{
    float r = __uint_as_float(0x7EF311C3u - __float_as_uint(x));
    r = r * fmaf(-x, r, 2.0f);
    r = r * fmaf(-x, r, 2.0f);
    return r;
}

__global__ void __launch_bounds__(128, 12) jb_kernel(
    const float* __restrict__ x,
    const float* __restrict__ g,
    const float* __restrict__ wgt,
    float* __restrict__ out)
{
    __shared__ float sm_t0[33], sm_t1[33], sm_t2[33], sm_x[33];
    __shared__ float sm_v0[33], sm_v1[33], sm_v2[33], sm_vx[33];

    int tid = threadIdx.x;
    int ql = tid & 31;
    int s  = tid >> 5;               // warp-uniform
    int blk = blockIdx.x;            // 2048 = 4 qb * 128 p * 4 b
    int qb = blk & 3;
    int p  = (blk >> 2) & 127;
    int b  = blk >> 9;
    int q  = qb * 32 + ql;

    const float* gb = g + (size_t)b * 3 * CH;
    const float* xb = x + b * (128 * 128);

    int hrow = (4 * p + s) * 512 + 4 * q;

    float4 c0 = *(const float4*)(gb + hrow);
    float4 c1 = *(const float4*)(gb + CH + hrow);
    float4 c2 = *(const float4*)(gb + 2 * CH + hrow);

    bool row2 = (p < 127);
    bool col2 = (q < 127);

    if (s == 1) {                    // publish first tap + x
        sm_t0[ql] = c0.y;
        sm_t1[ql] = c1.y;
        sm_t2[ql] = c2.y;
        sm_x[ql]  = xb[p * 128 + q];
        if (ql == 31) {              // q+1 halo (clamped; q==127 predicated off)
            int hq = col2 ? q + 1 : q;
            int oh = (4 * p + 1) * 512 + 4 * hq + 1;
            sm_t0[32] = gb[oh];
            sm_t1[32] = gb[oh + CH];
            sm_t2[32] = gb[oh + 2 * CH];
            sm_x[32]  = xb[p * 128 + hq];
        }
    }
    if (s == 3) {                    // publish second-row tap + x (clamped)
        int pr = row2 ? p + 1 : p;
        int ov = (4 * pr + 1) * 512 + 4 * q + 1;
        sm_v0[ql] = gb[ov];
        sm_v1[ql] = gb[ov + CH];
        sm_v2[ql] = gb[ov + 2 * CH];
        sm_vx[ql] = xb[pr * 128 + q];
        if (ql == 31) {
            int hq = col2 ? q + 1 : q;
            int ovh = (4 * pr + 1) * 512 + 4 * hq + 1;
            sm_v0[32] = gb[ovh];
            sm_v1[32] = gb[ovh + CH];
            sm_v2[32] = gb[ovh + 2 * CH];
            sm_vx[32] = xb[pr * 128 + hq];
        }
    }
    __syncthreads();

    float t0 = sm_t0[ql], t1 = sm_t1[ql], t2 = sm_t2[ql];
    float u0 = sm_t0[ql + 1], u1 = sm_t1[ql + 1], u2 = sm_t2[ql + 1];
    float x00 = sm_x[ql], x01 = sm_x[ql + 1];

    // weights for this output row (warp-uniform addresses)
    float wA0 = wgt[(s + 1) * 5 + 1] * x00;
    float wA1 = wgt[(s + 1) * 5 + 2] * x00;
    float wA2 = wgt[(s + 1) * 5 + 3] * x00;
    float wA3 = wgt[(s + 1) * 5 + 4] * x00;
    float wCol = wgt[(s + 1) * 5] * x01;

    float espS = (s == 1) ? 1.0f : ((s == 3) ? E4 : E1);

    float ctr0[4] = {c0.x, c0.y, c0.z, c0.w};
    float ctr1[4] = {c1.x, c1.y, c1.z, c1.w};
    float ctr2[4] = {c2.x, c2.y, c2.z, c2.w};
    float wAr[4]  = {wA0, wA1, wA2, wA3};
    const float espC[4] = {E1, 1.0f, E1, E4};

    float num[4], den[4];
#pragma unroll
    for (int r = 0; r < 4; r++) {
        float d0 = t0 - ctr0[r];
        float d1 = t1 - ctr1[r];
        float d2 = t2 - ctr2[r];
        float z = 0.125f * fmaf(d0, d0, fmaf(d1, d1, d2 * d2));
        float e = exp_neg_small(z) * (espS * espC[r]);
        den[r] = e;
        num[r] = e * wAr[r];
    }
    {   // second-col tap for r=3
        float h0 = u0 - ctr0[3];
        float h1 = u1 - ctr1[3];
        float h2 = u2 - ctr2[3];
        float z = 0.125f * fmaf(h0, h0, fmaf(h1, h1, h2 * h2));
        float e3 = exp_neg_small(z) * (espS * E4);
        if (col2) { den[3] += e3; num[3] += e3 * wCol; }
    }

    if (s == 3 && row2) {            // warp-uniform second-row taps
        float v0 = sm_v0[ql], v1 = sm_v1[ql], v2 = sm_v2[ql];
        float x10 = sm_vx[ql];
#pragma unroll
        for (int r = 0; r < 4; r++) {
            float f0 = v0 - ctr0[r];
            float f1 = v1 - ctr1[r];
            float f2 = v2 - ctr2[r];
            float z = 0.125f * fmaf(f0, f0, fmaf(f1, f1, f2 * f2));
            float e2 = exp_neg_small(z) * (E4 * espC[r]);
            den[r] += e2;
            num[r] += e2 * wgt[r + 1] * x10;
        }
        if (col2) {                  // corner tap
            float k0 = sm_v0[ql + 1] - ctr0[3];
            float k1 = sm_v1[ql + 1] - ctr1[3];
            float k2 = sm_v2[ql + 1] - ctr2[3];
            float zz = 0.125f * fmaf(k0, k0, fmaf(k1, k1, k2 * k2));
            float e4 = exp_neg_small(zz) * (E4 * E4);
            den[3] += e4;
            num[3] += e4 * wgt[0] * sm_vx[ql + 1];
        }
    }

    float4 o = make_float4(num[0] * fast_rcp(den[0]),
                           num[1] * fast_rcp(den[1]),
                           num[2] * fast_rcp(den[2]),
                           num[3] * fast_rcp(den[3]));
    *(float4*)(out + (size_t)b * CH + hrow) = o;
}

extern "C" void kernel_launch(void* const* d_in, const int* in_sizes, int n_in,
                              void* d_out, int out_size)
{
    const float* x   = (const float*)d_in[0];
    const float* g   = (const float*)d_in[1];
    const float* wgt = (const float*)d_in[2];
    float* out = (float*)d_out;

    // 2048 blocks: 4 qb * 128 p * 4 b ; 128 threads: 4 s-rows * 32 q
    jb_kernel<<<2048, 128>>>(x, g, wgt, out);
}

// round 9
// speedup vs baseline: 1.2330x; 1.2330x over previous
#include <cuda_runtime.h>
#include <cuda_bf16.h>

// JointBilateral upsample, S=4, K=5. Block = 256 threads covering a 4-row x
// 512-col output stripe. Thread (q, gsel) computes 8 pixels: rows {4p+gsel,
// 4p+gsel+2}, cols 4q..4q+3. Both rows share all tap/x values and index math.
//
// First tap (4p+1, 4q+1) == gsel=1 thread's rowA center .y (free).
// Second-row tap row (4p+5) loaded as 3 float4 (.y extract) by gsel=1 threads.
// Taps published via smem; q+1 neighbors read smem[q+1].
//
// e(tap) = exp(-0.125*||g_tap - g_ctr||^2) * exp(-0.005*((i-2)^2+(j-2)^2))
// out = sum(e * wgt[4-i][4-j] * x_tap) / sum(e)
// MUFU-free: cubic exp(-z) for z in [0,0.094], Newton reciprocal.

#define CH  (512 * 512)
#define E1  0.9950124791926823f   /* exp(-0.005) */
#define E4  0.9801986733067553f   /* exp(-0.020) */

__device__ __forceinline__ float exp_neg_small(float z)
{
    float p = fmaf(-0.16666667f, z, 0.5f);
    p = fmaf(p, z, -1.0f);
    return fmaf(p, z, 1.0f);
}

__device__ __forceinline__ float fast_rcp(float x)
{
    float r = __uint_as_float(0x7EF311C3u - __float_as_uint(x));
    r = r * fmaf(-x, r, 2.0f);
    r = r * fmaf(-x, r, 2.0f);
    return r;
}

__global__ void __launch_bounds__(256) jb_kernel(
    const float* __restrict__ x,
    const float* __restrict__ g,
    const float* __restrict__ wgt,
    float* __restrict__ out)
{
    __shared__ float sm_t0[129], sm_t1[129], sm_t2[129], sm_x[129];
    __shared__ float sm_v0[129], sm_v1[129], sm_v2[129], sm_vx[129];

    int tid  = threadIdx.x;
    int q    = tid & 127;
    int gsel = tid >> 7;              // 0: rows {0,2}; 1: rows {1,3}
    int blk  = blockIdx.x;            // 512 = 128 p * 4 b
    int p    = blk & 127;
    int b    = blk >> 7;

    const float* gb = g + (size_t)b * 3 * CH;
    const float* xb = x + b * (128 * 128);

    bool row2 = (p < 127);
    bool col2 = (q < 127);

    int rowA = (4 * p + gsel) * 512 + 4 * q;
    int rowB = rowA + 2 * 512;

    // ---- front-loaded center loads (6 float4) ----
    float4 a0 = *(const float4*)(gb + rowA);
    float4 a1 = *(const float4*)(gb + CH + rowA);
    float4 a2 = *(const float4*)(gb + 2 * CH + rowA);
    float4 e0 = *(const float4*)(gb + rowB);
    float4 e1 = *(const float4*)(gb + CH + rowB);
    float4 e2 = *(const float4*)(gb + 2 * CH + rowB);

    if (gsel == 1) {                  // rowA is row 4p+1: its .y IS the first tap
        sm_t0[q] = a0.y;
        sm_t1[q] = a1.y;
        sm_t2[q] = a2.y;
        sm_x[q]  = xb[p * 128 + q];
        // second-row tap row 4p+5 (clamped to 4p+1 at p==127), vectorized
        int vr = row2 ? (4 * p + 5) : (4 * p + 1);
        int ov = vr * 512 + 4 * q;
        float4 v0v = *(const float4*)(gb + ov);
        float4 v1v = *(const float4*)(gb + CH + ov);
        float4 v2v = *(const float4*)(gb + 2 * CH + ov);
        sm_v0[q] = v0v.y;
        sm_v1[q] = v1v.y;
        sm_v2[q] = v2v.y;
        sm_vx[q] = xb[(p + (row2 ? 1 : 0)) * 128 + q];
    }
    if (tid == 0) {
        sm_t0[128] = 0.f; sm_t1[128] = 0.f; sm_t2[128] = 0.f; sm_x[128] = 0.f;
        sm_v0[128] = 0.f; sm_v1[128] = 0.f; sm_v2[128] = 0.f; sm_vx[128] = 0.f;
    }
    __syncthreads();

    float t0 = sm_t0[q], t1 = sm_t1[q], t2 = sm_t2[q];
    float u0 = sm_t0[q + 1], u1 = sm_t1[q + 1], u2 = sm_t2[q + 1];
    float x00 = sm_x[q], x01 = sm_x[q + 1];

    const float espC[4] = {E1, 1.0f, E1, E4};
    const float espSTab[4] = {E1, 1.0f, E1, E4};

    size_t obase = (size_t)b * CH;

    // ================= row A (s' = gsel: 0 or 1) =================
    {
        int sp = gsel;
        float espS = espSTab[sp];
        const float* wr = wgt + (sp + 1) * 5;
        float wAr[4] = {wr[1] * x00, wr[2] * x00, wr[3] * x00, wr[4] * x00};
        float wCol = wr[0] * x01;
        float ctr0[4] = {a0.x, a0.y, a0.z, a0.w};
        float ctr1[4] = {a1.x, a1.y, a1.z, a1.w};
        float ctr2[4] = {a2.x, a2.y, a2.z, a2.w};

        float num[4], den[4];
#pragma unroll
        for (int r = 0; r < 4; r++) {
            float d0 = t0 - ctr0[r];
            float d1 = t1 - ctr1[r];
            float d2 = t2 - ctr2[r];
            float z = 0.125f * fmaf(d0, d0, fmaf(d1, d1, d2 * d2));
            float e = exp_neg_small(z) * (espS * espC[r]);
            den[r] = e;
            num[r] = e * wAr[r];
        }
        {
            float h0 = u0 - ctr0[3];
            float h1 = u1 - ctr1[3];
            float h2 = u2 - ctr2[3];
            float z = 0.125f * fmaf(h0, h0, fmaf(h1, h1, h2 * h2));
            float e3 = exp_neg_small(z) * (espS * E4);
            if (col2) { den[3] += e3; num[3] += e3 * wCol; }
        }
        float4 o = make_float4(num[0] * fast_rcp(den[0]),
                               num[1] * fast_rcp(den[1]),
                               num[2] * fast_rcp(den[2]),
                               num[3] * fast_rcp(den[3]));
        *(float4*)(out + obase + rowA) = o;
    }

    // ================= row B (s' = gsel+2: 2 or 3) =================
    {
        int sp = gsel + 2;
        float espS = espSTab[sp];
        const float* wr = wgt + (sp + 1) * 5;
        float wAr[4] = {wr[1] * x00, wr[2] * x00, wr[3] * x00, wr[4] * x00};
        float wCol = wr[0] * x01;
        float ctr0[4] = {e0.x, e0.y, e0.z, e0.w};
        float ctr1[4] = {e1.x, e1.y, e1.z, e1.w};
        float ctr2[4] = {e2.x, e2.y, e2.z, e2.w};

        float num[4], den[4];
#pragma unroll
        for (int r = 0; r < 4; r++) {
            float d0 = t0 - ctr0[r];
            float d1 = t1 - ctr1[r];
            float d2 = t2 - ctr2[r];
            float z = 0.125f * fmaf(d0, d0, fmaf(d1, d1, d2 * d2));
            float e = exp_neg_small(z) * (espS * espC[r]);
            den[r] = e;
            num[r] = e * wAr[r];
        }
        {
            float h0 = u0 - ctr0[3];
            float h1 = u1 - ctr1[3];
            float h2 = u2 - ctr2[3];
            float z = 0.125f * fmaf(h0, h0, fmaf(h1, h1, h2 * h2));
            float e3 = exp_neg_small(z) * (espS * E4);
            if (col2) { den[3] += e3; num[3] += e3 * wCol; }
        }

        if (gsel == 1 && row2) {      // s'==3: second-row taps (warp-uniform)
            float v0 = sm_v0[q], v1 = sm_v1[q], v2 = sm_v2[q];
            float x10 = sm_vx[q];
#pragma unroll
            for (int r = 0; r < 4; r++) {
                float f0 = v0 - ctr0[r];
                float f1 = v1 - ctr1[r];
                float f2 = v2 - ctr2[r];
                float z = 0.125f * fmaf(f0, f0, fmaf(f1, f1, f2 * f2));
                float e2x = exp_neg_small(z) * (E4 * espC[r]);
                den[r] += e2x;
                num[r] += e2x * wgt[r + 1] * x10;
            }
            if (col2) {               // corner tap
                float k0 = sm_v0[q + 1] - ctr0[3];
                float k1 = sm_v1[q + 1] - ctr1[3];
                float k2 = sm_v2[q + 1] - ctr2[3];
                float zz = 0.125f * fmaf(k0, k0, fmaf(k1, k1, k2 * k2));
                float e4x = exp_neg_small(zz) * (E4 * E4);
                den[3] += e4x;
                num[3] += e4x * wgt[0] * sm_vx[q + 1];
            }
        }

        float4 o = make_float4(num[0] * fast_rcp(den[0]),
                               num[1] * fast_rcp(den[1]),
                               num[2] * fast_rcp(den[2]),
                               num[3] * fast_rcp(den[3]));
        *(float4*)(out + obase + rowB) = o;
    }
}

extern "C" void kernel_launch(void* const* d_in, const int* in_sizes, int n_in,
                              void* d_out, int out_size)
{
    const float* x   = (const float*)d_in[0];
    const float* g   = (const float*)d_in[1];
    const float* wgt = (const float*)d_in[2];
    float* out = (float*)d_out;

    // 512 blocks: 128 p * 4 b ; 256 threads: 2 row-groups * 128 q
    jb_kernel<<<512, 256>>>(x, g, wgt, out);
}

// round 11
// speedup vs baseline: 1.6618x; 1.3478x over previous
#include <cuda_runtime.h>
#include <cuda_bf16.h>

// JointBilateral upsample, S=4, K=5. One thread = 8 output pixels: rows
// {4p+gsel, 4p+gsel+2}, cols 4q..4q+3. Both rows share tap values, x values
// and index math. No smem, no barrier: taps are per-thread loads (warm-L2
// hits; tap rows are other warps' center rows).
//
// e(tap) = exp(-0.125*||g_tap - g_ctr||^2) * exp(-0.005*((i-2)^2+(j-2)^2))
// out = sum(e * wgt[4-i][4-j] * x_tap) / sum(e)
// MUFU-free: cubic exp(-z) for z in [0,0.094], Newton reciprocal.

#define CH  (512 * 512)
#define E1  0.9950124791926823f   /* exp(-0.005) */
#define E4  0.9801986733067553f   /* exp(-0.020) */

__device__ __forceinline__ float exp_neg_small(float z)
{
    float p = fmaf(-0.16666667f, z, 0.5f);
    p = fmaf(p, z, -1.0f);
    return fmaf(p, z, 1.0f);
}

__device__ __forceinline__ float fast_rcp(float x)
{
    float r = __uint_as_float(0x7EF311C3u - __float_as_uint(x));
    r = r * fmaf(-x, r, 2.0f);
    r = r * fmaf(-x, r, 2.0f);
    return r;
}

__global__ void __launch_bounds__(128) jb_kernel(
    const float* __restrict__ x,
    const float* __restrict__ g,
    const float* __restrict__ wgt,
    float* __restrict__ out)
{
    int tid  = threadIdx.x;
    int ql   = tid & 63;
    int gsel = tid >> 6;              // 0: rows {0,2}; 1: rows {1,3}
    int blk  = blockIdx.x;            // 1024 = 2 qh * 128 p * 4 b
    int qh   = blk & 1;
    int p    = (blk >> 1) & 127;
    int b    = blk >> 8;
    int q    = qh * 64 + ql;

    const float* gb = g + (size_t)b * 3 * CH;
    const float* xb = x + b * (128 * 128);

    bool row2 = (p < 127);
    bool col2 = (q < 127);
    int dq = col2 ? 4 : 0;
    int cq = col2 ? 1 : 0;

    int rowA = (4 * p + gsel) * 512 + 4 * q;
    int rowB = rowA + 2 * 512;
    int o00  = (4 * p + 1) * 512 + 4 * q + 1;

    // ---- front-loaded loads ----
    float4 a0 = *(const float4*)(gb + rowA);
    float4 a1 = *(const float4*)(gb + CH + rowA);
    float4 a2 = *(const float4*)(gb + 2 * CH + rowA);
    float4 e0 = *(const float4*)(gb + rowB);
    float4 e1 = *(const float4*)(gb + CH + rowB);
    float4 e2 = *(const float4*)(gb + 2 * CH + rowB);

    float t0 = gb[o00];
    float t1 = gb[o00 + CH];
    float t2 = gb[o00 + 2 * CH];
    float u0 = gb[o00 + dq];
    float u1 = gb[o00 + dq + CH];
    float u2 = gb[o00 + dq + 2 * CH];

    int xo = p * 128 + q;
    float x00 = xb[xo];
    float x01 = xb[xo + cq];

    // second-row taps only needed by gsel==1 (row 4p+3); warp-uniform branch
    float v0 = 0.f, v1 = 0.f, v2 = 0.f, z0 = 0.f, z1 = 0.f, z2 = 0.f;
    float x10 = 0.f, x11 = 0.f;
    if (gsel == 1) {
        int dr = row2 ? 4 * 512 : 0;
        v0 = gb[o00 + dr];
        v1 = gb[o00 + dr + CH];
        v2 = gb[o00 + dr + 2 * CH];
        z0 = gb[o00 + dr + dq];
        z1 = gb[o00 + dr + dq + CH];
        z2 = gb[o00 + dr + dq + 2 * CH];
        int cp = row2 ? 1 : 0;
        x10 = xb[xo + cp * 128];
        x11 = xb[xo + cp * 128 + cq];
    }

    const float espC[4]    = {E1, 1.0f, E1, E4};
    const float espSTab[4] = {E1, 1.0f, E1, E4};
    size_t obase = (size_t)b * CH;

    // ================= row A (sp = gsel) =================
    {
        int sp = gsel;
        float espS = espSTab[sp];
        const float* wr = wgt + (sp + 1) * 5;
        float wAr[4] = {wr[1] * x00, wr[2] * x00, wr[3] * x00, wr[4] * x00};
        float wCol = wr[0] * x01;
        float ctr0[4] = {a0.x, a0.y, a0.z, a0.w};
        float ctr1[4] = {a1.x, a1.y, a1.z, a1.w};
        float ctr2[4] = {a2.x, a2.y, a2.z, a2.w};

        float num[4], den[4];
#pragma unroll
        for (int r = 0; r < 4; r++) {
            float d0 = t0 - ctr0[r];
            float d1 = t1 - ctr1[r];
            float d2 = t2 - ctr2[r];
            float zv = 0.125f * fmaf(d0, d0, fmaf(d1, d1, d2 * d2));
            float e = exp_neg_small(zv) * (espS * espC[r]);
            den[r] = e;
            num[r] = e * wAr[r];
        }
        {
            float h0 = u0 - ctr0[3];
            float h1 = u1 - ctr1[3];
            float h2 = u2 - ctr2[3];
            float zv = 0.125f * fmaf(h0, h0, fmaf(h1, h1, h2 * h2));
            float e3 = exp_neg_small(zv) * (espS * E4);
            if (col2) { den[3] += e3; num[3] += e3 * wCol; }
        }
        float4 o = make_float4(num[0] * fast_rcp(den[0]),
                               num[1] * fast_rcp(den[1]),
                               num[2] * fast_rcp(den[2]),
                               num[3] * fast_rcp(den[3]));
        *(float4*)(out + obase + rowA) = o;
    }

    // ================= row B (sp = gsel + 2) =================
    {
        int sp = gsel + 2;
        float espS = espSTab[sp];
        const float* wr = wgt + (sp + 1) * 5;
        float wAr[4] = {wr[1] * x00, wr[2] * x00, wr[3] * x00, wr[4] * x00};
        float wCol = wr[0] * x01;
        float ctr0[4] = {e0.x, e0.y, e0.z, e0.w};
        float ctr1[4] = {e1.x, e1.y, e1.z, e1.w};
        float ctr2[4] = {e2.x, e2.y, e2.z, e2.w};

        float num[4], den[4];
#pragma unroll
        for (int r = 0; r < 4; r++) {
            float d0 = t0 - ctr0[r];
            float d1 = t1 - ctr1[r];
            float d2 = t2 - ctr2[r];
            float zv = 0.125f * fmaf(d0, d0, fmaf(d1, d1, d2 * d2));
            float e = exp_neg_small(zv) * (espS * espC[r]);
            den[r] = e;
            num[r] = e * wAr[r];
        }
        {
            float h0 = u0 - ctr0[3];
            float h1 = u1 - ctr1[3];
            float h2 = u2 - ctr2[3];
            float zv = 0.125f * fmaf(h0, h0, fmaf(h1, h1, h2 * h2));
            float e3 = exp_neg_small(zv) * (espS * E4);
            if (col2) { den[3] += e3; num[3] += e3 * wCol; }
        }

        if (gsel == 1 && row2) {      // row 4p+3: second-row taps (warp-uniform)
#pragma unroll
            for (int r = 0; r < 4; r++) {
                float f0 = v0 - ctr0[r];
                float f1 = v1 - ctr1[r];
                float f2 = v2 - ctr2[r];
                float zv = 0.125f * fmaf(f0, f0, fmaf(f1, f1, f2 * f2));
                float e2x = exp_neg_small(zv) * (E4 * espC[r]);
                den[r] += e2x;
                num[r] += e2x * wgt[r + 1] * x10;
            }
            if (col2) {               // corner tap
                float k0 = z0 - ctr0[3];
                float k1 = z1 - ctr1[3];
                float k2 = z2 - ctr2[3];
                float zz = 0.125f * fmaf(k0, k0, fmaf(k1, k1, k2 * k2));
                float e4x = exp_neg_small(zz) * (E4 * E4);
                den[3] += e4x;
                num[3] += e4x * wgt[0] * x11;
            }
        }

        float4 o = make_float4(num[0] * fast_rcp(den[0]),
                               num[1] * fast_rcp(den[1]),
                               num[2] * fast_rcp(den[2]),
                               num[3] * fast_rcp(den[3]));
        *(float4*)(out + obase + rowB) = o;
    }
}

extern "C" void kernel_launch(void* const* d_in, const int* in_sizes, int n_in,
                              void* d_out, int out_size)
{
    const float* x   = (const float*)d_in[0];
    const float* g   = (const float*)d_in[1];
    const float* wgt = (const float*)d_in[2];
    float* out = (float*)d_out;

    // 1024 blocks: 2 qh * 128 p * 4 b ; 128 threads: 2 row-groups * 64 q
    jb_kernel<<<1024, 128>>>(x, g, wgt, out);
}